// round 11
// baseline (speedup 1.0000x reference)
#include <cuda_runtime.h>
#include <cuda_bf16.h>
#include <mma.h>

using namespace nvcuda;

constexpr int DMAX = 128;
constexpr int NMAX = 50000;
constexpr int EMAX = 1600000;

__device__ __nv_bfloat16 g_Pb[(size_t)NMAX * DMAX];
__device__ float g_pool0[(size_t)NMAX * DMAX];
__device__ float g_pool1[(size_t)NMAX * DMAX];
__device__ uint4 g_aib[EMAX];          // add_info as 4 replicated bf16x2 per edge
__device__ __nv_bfloat16 g_Wh[3 * 128 * 128];
__device__ __nv_bfloat16 g_Wl[3 * 128 * 128];
__device__ float g_Wc10[128 * 128];
__device__ float g_wf0[128];
__device__ float g_wf1[128];
__device__ float g_c1[128];
__device__ float g_cf[1];

__device__ __forceinline__ void split_bf16(float v, __nv_bfloat16& h, __nv_bfloat16& l) {
    h = __float2bfloat16(v);
    l = __float2bfloat16(v - __bfloat162float(h));
}

// ---------------------------------------------------------------------------
// prepA: combined-weight precompute (fp32).
// ---------------------------------------------------------------------------
__global__ void prepA_kernel(const float* __restrict__ Wo0, const float* __restrict__ Wb1,
                             const float* __restrict__ Wo1, const float* __restrict__ Wf,
                             const float* __restrict__ bb1, const float* __restrict__ bo0,
                             const float* __restrict__ bo1, const float* __restrict__ bf,
                             float* __restrict__ Wc10, float* __restrict__ wf0,
                             float* __restrict__ wf1, float* __restrict__ c1,
                             float* __restrict__ cf) {
    int g = blockIdx.x, tid = threadIdx.x;
    if (g < 64) {
        int idx = g * 256 + tid;
        int i = idx >> 7, j = idx & 127;
        float s = 0.f;
        for (int k = 0; k < 128; k++) s = fmaf(Wo0[i * 128 + k], Wb1[k * 128 + j], s);
        Wc10[idx] = s;
    } else if (g == 64) {
        if (tid < 128) {
            float s = 0.f;
            for (int k = 0; k < 128; k++) s = fmaf(Wo0[tid * 128 + k], Wf[k], s);
            wf0[tid] = s;
        } else {
            int r = tid - 128;
            float s = 0.f;
            for (int k = 0; k < 128; k++) s = fmaf(Wo1[r * 128 + k], Wf[k], s);
            wf1[r] = s;
        }
    } else {
        if (tid < 128) {
            float s = 0.f;
            for (int k = 0; k < 128; k++) s = fmaf(bo0[k], Wb1[k * 128 + tid], s);
            c1[tid] = s + bb1[tid];
        } else if (tid == 128) {
            float s = 0.f;
            for (int k = 0; k < 128; k++) s = fmaf(bo0[k] + bo1[k], Wf[k], s);
            cf[0] = s + bf[0];
        }
    }
}

// prepB: split 3 matrices into bf16 hi/lo.
__global__ void split_w_kernel(const float* __restrict__ W0, const float* __restrict__ W1,
                               const float* __restrict__ W2,
                               __nv_bfloat16* __restrict__ Wh, __nv_bfloat16* __restrict__ Wl) {
    int idx = blockIdx.x * blockDim.x + threadIdx.x;
    if (idx >= 3 * 4096) return;
    int m = idx >> 12;
    int off = idx & 4095;
    const float* W = (m == 0) ? W0 : (m == 1) ? W1 : W2;
    float4 v = reinterpret_cast<const float4*>(W)[off];
    __nv_bfloat16 h[4], l[4];
    split_bf16(v.x, h[0], l[0]); split_bf16(v.y, h[1], l[1]);
    split_bf16(v.z, h[2], l[2]); split_bf16(v.w, h[3], l[3]);
    reinterpret_cast<uint2*>(Wh)[idx] = *reinterpret_cast<uint2*>(h);
    reinterpret_cast<uint2*>(Wl)[idx] = *reinterpret_cast<uint2*>(l);
}

// prepC: add_info -> 4 replicated bf16x2 per edge.
__global__ void cvt_ai_kernel(const float4* __restrict__ ai, uint4* __restrict__ aib, int E) {
    int e = blockIdx.x * blockDim.x + threadIdx.x;
    if (e >= E) return;
    float4 a = __ldg(ai + e);
    __nv_bfloat162 x = __float2bfloat162_rn(a.x);
    __nv_bfloat162 y = __float2bfloat162_rn(a.y);
    __nv_bfloat162 z = __float2bfloat162_rn(a.z);
    __nv_bfloat162 w = __float2bfloat162_rn(a.w);
    uint4 o;
    o.x = *reinterpret_cast<unsigned*>(&x);
    o.y = *reinterpret_cast<unsigned*>(&y);
    o.z = *reinterpret_cast<unsigned*>(&z);
    o.w = *reinterpret_cast<unsigned*>(&w);
    aib[e] = o;
}

// ---------------------------------------------------------------------------
// bf16 tensor-core GEMM (unchanged — proven).
// ---------------------------------------------------------------------------
constexpr int KC   = 32;
constexpr int LDAB = 40;
constexpr int LDBB = 136;
constexpr int LDC  = 132;
constexpr int SM_AH = 0;
constexpr int SM_AL = SM_AH + 128 * LDAB;
constexpr int SM_BH = SM_AL + 128 * LDAB;
constexpr int SM_BL = SM_BH + KC * LDBB;
constexpr int SMEM_BF16 = SM_BL + KC * LDBB;
static_assert(SMEM_BF16 * 2 >= 64 * LDC * 4, "C stage fits");

template <bool OUT_BF16, bool DUAL>
__global__ __launch_bounds__(256, 2) void gemm_kernel(
        const float* __restrict__ A1,
        const __nv_bfloat16* __restrict__ Wh1, const __nv_bfloat16* __restrict__ Wl1,
        const float* __restrict__ A2,
        const __nv_bfloat16* __restrict__ Wh2, const __nv_bfloat16* __restrict__ Wl2,
        const float* __restrict__ bias,
        float* __restrict__ Cf, __nv_bfloat16* __restrict__ Cb, int Nrows) {
    __shared__ __align__(16) char smem_raw[SMEM_BF16 * 2];
    __nv_bfloat16* sb = reinterpret_cast<__nv_bfloat16*>(smem_raw);
    __nv_bfloat16* sAh = sb + SM_AH;
    __nv_bfloat16* sAl = sb + SM_AL;
    __nv_bfloat16* sBh = sb + SM_BH;
    __nv_bfloat16* sBl = sb + SM_BL;
    float* sC = reinterpret_cast<float*>(smem_raw);

    const int tid  = threadIdx.x;
    const int lane = tid & 31;
    const int warp = tid >> 5;
    const int wm = warp >> 2;
    const int wn = warp & 3;
    const int row0 = blockIdx.x * 128;

    wmma::fragment<wmma::accumulator, 16, 16, 16, float> acc[4][2];
#pragma unroll
    for (int i = 0; i < 4; i++)
#pragma unroll
        for (int j = 0; j < 2; j++) wmma::fill_fragment(acc[i][j], 0.0f);

    const int nPhase = DUAL ? 2 : 1;
#pragma unroll 1
    for (int ph = 0; ph < nPhase; ph++) {
        const float* A = (ph == 0) ? A1 : A2;
        const __nv_bfloat16* WhP = (ph == 0) ? Wh1 : Wh2;
        const __nv_bfloat16* WlP = (ph == 0) ? Wl1 : Wl2;
        const bool doSplit = (ph == 0);

#pragma unroll 1
        for (int k0 = 0; k0 < 128; k0 += KC) {
#pragma unroll
            for (int it = 0; it < 4; it++) {
                int idx = tid + it * 256;
                int r = idx >> 3;
                int c4 = idx & 7;
                float4 v = make_float4(0.f, 0.f, 0.f, 0.f);
                if (row0 + r < Nrows)
                    v = reinterpret_cast<const float4*>(A + (size_t)(row0 + r) * 128 + k0)[c4];
                __nv_bfloat16 h[4], l[4];
                split_bf16(v.x, h[0], l[0]); split_bf16(v.y, h[1], l[1]);
                split_bf16(v.z, h[2], l[2]); split_bf16(v.w, h[3], l[3]);
                *reinterpret_cast<uint2*>(sAh + r * LDAB + c4 * 4) = *reinterpret_cast<uint2*>(h);
                if (doSplit)
                    *reinterpret_cast<uint2*>(sAl + r * LDAB + c4 * 4) = *reinterpret_cast<uint2*>(l);
            }
#pragma unroll
            for (int it = 0; it < 2; it++) {
                int idx = tid + it * 256;
                int r = idx >> 4;
                int c8 = idx & 15;
                const uint4* srcH = reinterpret_cast<const uint4*>(WhP + (size_t)(k0 + r) * 128) + c8;
                const uint4* srcL = reinterpret_cast<const uint4*>(WlP + (size_t)(k0 + r) * 128) + c8;
                *reinterpret_cast<uint4*>(sBh + r * LDBB + c8 * 8) = __ldg(srcH);
                *reinterpret_cast<uint4*>(sBl + r * LDBB + c8 * 8) = __ldg(srcL);
            }
            __syncthreads();

#pragma unroll
            for (int ks = 0; ks < 2; ks++) {
                const int koff = ks * 16;
                wmma::fragment<wmma::matrix_b, 16, 16, 16, __nv_bfloat16, wmma::row_major> bh[2], bl[2];
#pragma unroll
                for (int j = 0; j < 2; j++) {
                    wmma::load_matrix_sync(bh[j], sBh + koff * LDBB + wn * 32 + j * 16, LDBB);
                    wmma::load_matrix_sync(bl[j], sBl + koff * LDBB + wn * 32 + j * 16, LDBB);
                }
#pragma unroll
                for (int i = 0; i < 4; i++) {
                    wmma::fragment<wmma::matrix_a, 16, 16, 16, __nv_bfloat16, wmma::row_major> ah, al;
                    wmma::load_matrix_sync(ah, sAh + (wm * 64 + i * 16) * LDAB + koff, LDAB);
                    if (doSplit)
                        wmma::load_matrix_sync(al, sAl + (wm * 64 + i * 16) * LDAB + koff, LDAB);
#pragma unroll
                    for (int j = 0; j < 2; j++) {
                        wmma::mma_sync(acc[i][j], ah, bh[j], acc[i][j]);
                        if (doSplit) wmma::mma_sync(acc[i][j], al, bh[j], acc[i][j]);
                        wmma::mma_sync(acc[i][j], ah, bl[j], acc[i][j]);
                    }
                }
            }
            __syncthreads();
        }
    }

#pragma unroll
    for (int half = 0; half < 2; half++) {
        __syncthreads();
        if (wm == half) {
#pragma unroll
            for (int i = 0; i < 4; i++)
#pragma unroll
                for (int j = 0; j < 2; j++)
                    wmma::store_matrix_sync(sC + (i * 16) * LDC + wn * 32 + j * 16,
                                            acc[i][j], LDC, wmma::mem_row_major);
        }
        __syncthreads();
#pragma unroll
        for (int it = 0; it < 8; it++) {
            int idx = tid + it * 256;
            int r = idx >> 5;
            int c4 = idx & 31;
            int grow = row0 + half * 64 + r;
            if (grow < Nrows) {
                float4 o = *reinterpret_cast<float4*>(sC + r * LDC + c4 * 4);
                float4 bv = reinterpret_cast<const float4*>(bias)[c4];
                o.x += bv.x; o.y += bv.y; o.z += bv.z; o.w += bv.w;
                if (OUT_BF16) {
                    __nv_bfloat16 b4[4];
                    b4[0] = __float2bfloat16(o.x); b4[1] = __float2bfloat16(o.y);
                    b4[2] = __float2bfloat16(o.z); b4[3] = __float2bfloat16(o.w);
                    reinterpret_cast<uint2*>(Cb + (size_t)grow * 128)[c4] =
                        *reinterpret_cast<uint2*>(b4);
                } else {
                    reinterpret_cast<float4*>(Cf + (size_t)grow * 128)[c4] = o;
                }
            }
        }
    }
}

// ---------------------------------------------------------------------------
// Edge kernel v3: one edge per HALF-WARP (16 lanes x 16B = full 128-col row
// via LDG.128). A warp processes 2 edges/iteration, 64 edges per range.
// Math: 16 HFMA2 + 4 HMAX2 per lane per iteration (2 edges).
// Segment logic per half-warp; fast-path warp vote, rare divergent flush.
// atomicMax on int bits valid for nonnegative floats; pooled init 0.
// ---------------------------------------------------------------------------
constexpr int PF2 = 4;   // prefetch depth in iterations (= 8 edges lookahead)

__device__ __forceinline__ void flush4(float* pooled, int seg, int cl,
                                       const __nv_bfloat162* v) {
    if (seg < 0) return;
    int* p = reinterpret_cast<int*>(pooled + (size_t)seg * 128 + cl * 8);
#pragma unroll
    for (int j = 0; j < 4; j++) {
        float2 f = __bfloat1622float2(v[j]);
        if (f.x > 0.f) atomicMax(p + 2 * j + 0, __float_as_int(f.x));
        if (f.y > 0.f) atomicMax(p + 2 * j + 1, __float_as_int(f.y));
    }
}

__global__ __launch_bounds__(256) void edge_kernel(
        const uint4* __restrict__ P4,      // N x 16 uint4 (bf16 rows, 256B)
        const uint4* __restrict__ aib,
        const int* __restrict__ nb, const int* __restrict__ seg,
        const float* __restrict__ Wba, float* __restrict__ pooled, int E) {
    // Weights as bf162: w2[row][c2], c2 = col/2 (64 entries per row)
    __shared__ __nv_bfloat162 wsh2[4][64];
    const int tid = threadIdx.x;
    if (tid < 128) {
        int r = tid >> 5, c = tid & 31;
        float4 w = reinterpret_cast<const float4*>(Wba)[tid];
        wsh2[r][2 * c + 0] = __floats2bfloat162_rn(w.x, w.y);
        wsh2[r][2 * c + 1] = __floats2bfloat162_rn(w.z, w.w);
    }
    __syncthreads();

    const int lane = tid & 31;
    const int warp = tid >> 5;
    const int hl = lane >> 4;          // which edge of the pair
    const int cl = lane & 15;          // col group: cols [8*cl, 8*cl+8)

    // Per-lane weight registers: 4 coeffs x 4 bf162 (8 cols).
    __nv_bfloat162 wreg[4][4];
#pragma unroll
    for (int a = 0; a < 4; a++)
#pragma unroll
        for (int j = 0; j < 4; j++) wreg[a][j] = wsh2[a][4 * cl + j];
    const __nv_bfloat162 zero2 = __float2bfloat162_rn(0.f);

    const int base = (blockIdx.x * (blockDim.x >> 5) + warp) * 64;
    if (base >= E) return;
    const int cnt = min(64, E - base);

    __nv_bfloat162 vmax[4] = {zero2, zero2, zero2, zero2};
    int cur = -1;

    if (cnt == 64) {
        uint4 praw[PF2];
#pragma unroll
        for (int k = 0; k < PF2; k++) {
            int n = __ldg(nb + base + 2 * k + hl);
            praw[k] = __ldg(P4 + (size_t)n * 16 + cl);
        }
#pragma unroll
        for (int i = 0; i < 32; i++) {
            int e = base + 2 * i + hl;
            int s = __ldg(seg + e);
            uint4 ar = __ldg(aib + e);
            __nv_bfloat162 ax = *reinterpret_cast<__nv_bfloat162*>(&ar.x);
            __nv_bfloat162 ay = *reinterpret_cast<__nv_bfloat162*>(&ar.y);
            __nv_bfloat162 az = *reinterpret_cast<__nv_bfloat162*>(&ar.z);
            __nv_bfloat162 aw = *reinterpret_cast<__nv_bfloat162*>(&ar.w);
            uint4 pr = praw[i & (PF2 - 1)];
            __nv_bfloat162 h[4];
            h[0] = *reinterpret_cast<__nv_bfloat162*>(&pr.x);
            h[1] = *reinterpret_cast<__nv_bfloat162*>(&pr.y);
            h[2] = *reinterpret_cast<__nv_bfloat162*>(&pr.z);
            h[3] = *reinterpret_cast<__nv_bfloat162*>(&pr.w);
#pragma unroll
            for (int j = 0; j < 4; j++) {
                h[j] = __hfma2(ax, wreg[0][j], h[j]);
                h[j] = __hfma2(ay, wreg[1][j], h[j]);
                h[j] = __hfma2(az, wreg[2][j], h[j]);
                h[j] = __hfma2(aw, wreg[3][j], h[j]);
            }

            bool changed = (s != cur);
            if (__any_sync(0xFFFFFFFFu, changed)) {
                if (changed) {
                    flush4(pooled, cur, cl, vmax);
                    cur = s;
#pragma unroll
                    for (int j = 0; j < 4; j++) vmax[j] = __hmax2(h[j], zero2);
                } else {
#pragma unroll
                    for (int j = 0; j < 4; j++) vmax[j] = __hmax2(vmax[j], h[j]);
                }
            } else {
#pragma unroll
                for (int j = 0; j < 4; j++) vmax[j] = __hmax2(vmax[j], h[j]);
            }

            if (i + PF2 < 32) {
                int n = __ldg(nb + e + 2 * PF2);
                praw[i & (PF2 - 1)] = __ldg(P4 + (size_t)n * 16 + cl);
            }
        }
    } else {
        for (int i = 0; i < 32; i++) {
            int eoff = 2 * i + hl;
            if (eoff >= cnt) break;       // divergent exit OK (no votes below)
            int e = base + eoff;
            int s = __ldg(seg + e);
            int n = __ldg(nb + e);
            uint4 ar = __ldg(aib + e);
            __nv_bfloat162 ax = *reinterpret_cast<__nv_bfloat162*>(&ar.x);
            __nv_bfloat162 ay = *reinterpret_cast<__nv_bfloat162*>(&ar.y);
            __nv_bfloat162 az = *reinterpret_cast<__nv_bfloat162*>(&ar.z);
            __nv_bfloat162 aw = *reinterpret_cast<__nv_bfloat162*>(&ar.w);
            uint4 pr = __ldg(P4 + (size_t)n * 16 + cl);
            __nv_bfloat162 h[4];
            h[0] = *reinterpret_cast<__nv_bfloat162*>(&pr.x);
            h[1] = *reinterpret_cast<__nv_bfloat162*>(&pr.y);
            h[2] = *reinterpret_cast<__nv_bfloat162*>(&pr.z);
            h[3] = *reinterpret_cast<__nv_bfloat162*>(&pr.w);
#pragma unroll
            for (int j = 0; j < 4; j++) {
                h[j] = __hfma2(ax, wreg[0][j], h[j]);
                h[j] = __hfma2(ay, wreg[1][j], h[j]);
                h[j] = __hfma2(az, wreg[2][j], h[j]);
                h[j] = __hfma2(aw, wreg[3][j], h[j]);
            }
            if (s != cur) {
                flush4(pooled, cur, cl, vmax);
                cur = s;
#pragma unroll
                for (int j = 0; j < 4; j++) vmax[j] = __hmax2(h[j], zero2);
            } else {
#pragma unroll
                for (int j = 0; j < 4; j++) vmax[j] = __hmax2(vmax[j], h[j]);
            }
        }
    }
    flush4(pooled, cur, cl, vmax);
}

// ---------------------------------------------------------------------------
// Final: out[n] = interp[n]@Wf + pool0[n]@wf0 + pool1[n]@wf1 + cf
// ---------------------------------------------------------------------------
__global__ void final_kernel(const float* __restrict__ interp,
                             const float* __restrict__ pool0,
                             const float* __restrict__ pool1,
                             const float* __restrict__ Wf,
                             const float* __restrict__ wf0,
                             const float* __restrict__ wf1,
                             const float* __restrict__ cf,
                             float* __restrict__ out, int N) {
    int gwarp = (blockIdx.x * blockDim.x + threadIdx.x) >> 5;
    int lane = threadIdx.x & 31;
    if (gwarp >= N) return;
    float4 xv = reinterpret_cast<const float4*>(interp + (size_t)gwarp * 128)[lane];
    float4 p0 = reinterpret_cast<const float4*>(pool0 + (size_t)gwarp * 128)[lane];
    float4 p1 = reinterpret_cast<const float4*>(pool1 + (size_t)gwarp * 128)[lane];
    float4 wv = reinterpret_cast<const float4*>(Wf)[lane];
    float4 v0 = reinterpret_cast<const float4*>(wf0)[lane];
    float4 v1 = reinterpret_cast<const float4*>(wf1)[lane];
    float s = xv.x * wv.x + xv.y * wv.y + xv.z * wv.z + xv.w * wv.w
            + p0.x * v0.x + p0.y * v0.y + p0.z * v0.z + p0.w * v0.w
            + p1.x * v1.x + p1.y * v1.y + p1.z * v1.z + p1.w * v1.w;
#pragma unroll
    for (int o = 16; o; o >>= 1) s += __shfl_xor_sync(0xFFFFFFFFu, s, o);
    if (lane == 0) out[gwarp] = s + cf[0];
}

// ---------------------------------------------------------------------------
extern "C" void kernel_launch(void* const* d_in, const int* in_sizes, int n_in,
                              void* d_out, int out_size) {
    const float* interpolated = (const float*)d_in[0];
    const float* add_info     = (const float*)d_in[1];
    const int*   nb           = (const int*)d_in[2];
    const int*   seg          = (const int*)d_in[3];
    const float* Wb0 = (const float*)d_in[4];
    const float* bb0 = (const float*)d_in[5];
    const float* Wo0 = (const float*)d_in[6];
    const float* bo0 = (const float*)d_in[7];
    const float* Wb1 = (const float*)d_in[8];
    const float* bb1 = (const float*)d_in[9];
    const float* Wo1 = (const float*)d_in[10];
    const float* bo1 = (const float*)d_in[11];
    const float* Wf  = (const float*)d_in[12];
    const float* bf  = (const float*)d_in[13];

    const int N = in_sizes[0] / 128;
    const int E = in_sizes[2];

    __nv_bfloat16 *Pb, *Wh, *Wl;
    float *pool0, *pool1, *Wc10, *wf0, *wf1, *c1, *cf;
    uint4* aib;
    cudaGetSymbolAddress((void**)&Pb,    g_Pb);
    cudaGetSymbolAddress((void**)&pool0, g_pool0);
    cudaGetSymbolAddress((void**)&pool1, g_pool1);
    cudaGetSymbolAddress((void**)&aib,   g_aib);
    cudaGetSymbolAddress((void**)&Wh,    g_Wh);
    cudaGetSymbolAddress((void**)&Wl,    g_Wl);
    cudaGetSymbolAddress((void**)&Wc10,  g_Wc10);
    cudaGetSymbolAddress((void**)&wf0,   g_wf0);
    cudaGetSymbolAddress((void**)&wf1,   g_wf1);
    cudaGetSymbolAddress((void**)&c1,    g_c1);
    cudaGetSymbolAddress((void**)&cf,    g_cf);

    const int gemmGrid = (N + 127) / 128;
    const int edgeGrid = (E + 511) / 512;    // 8 warps/CTA x 64 edges/warp
    const size_t poolBytes = (size_t)N * 128 * sizeof(float);
    const uint4* P4 = (const uint4*)Pb;
    const int WM = 128 * 128;

    prepA_kernel<<<66, 256>>>(Wo0, Wb1, Wo1, Wf, bb1, bo0, bo1, bf,
                              Wc10, wf0, wf1, c1, cf);
    split_w_kernel<<<48, 256>>>(Wb0, Wb1, Wc10, Wh, Wl);
    cvt_ai_kernel<<<(E + 255) / 256, 256>>>((const float4*)add_info, aib, E);
    cudaMemsetAsync(pool0, 0, poolBytes);
    cudaMemsetAsync(pool1, 0, poolBytes);

    // Block 0: P0 = interp@Wb0top + bb0
    gemm_kernel<true, false><<<gemmGrid, 256>>>(
        interpolated, Wh + 0 * WM, Wl + 0 * WM,
        nullptr, nullptr, nullptr, bb0, nullptr, Pb, N);
    edge_kernel<<<edgeGrid, 256>>>(P4, aib, nb, seg, Wb0 + 128 * 128, pool0, E);

    // Mid (fused): P1 = interp@Wb1top + pool0@Wc10 + c1
    gemm_kernel<true, true><<<gemmGrid, 256>>>(
        interpolated, Wh + 1 * WM, Wl + 1 * WM,
        pool0, Wh + 2 * WM, Wl + 2 * WM, c1, nullptr, Pb, N);
    edge_kernel<<<edgeGrid, 256>>>(P4, aib, nb, seg, Wb1 + 128 * 128, pool1, E);

    // Final: out = interp@Wf + pool0@wf0 + pool1@wf1 + cf
    final_kernel<<<(N * 32 + 255) / 256, 256>>>(
        interpolated, pool0, pool1, Wf, wf0, wf1, cf, (float*)d_out, N);
}